// round 2
// baseline (speedup 1.0000x reference)
#include <cuda_runtime.h>
#include <cstdint>

// ---------------------------------------------------------------------------
// TCNet: B=128, NV=100, NQ=14, NA=10, V_DIM=2048, Q_DIM=1024, A_DIM=1024,
//        H_DIM=512, RANK=32, HD=16, G=2
//
// Reference einsum: 'rijkg,bnvi,bnqj,bnak->bvqag'
//   NOTE: r (T's rank axis) and n (modality rank axis) are INDEPENDENT sums.
//   => Tbar[i,j,k,g] = sum_r T[r,i,j,k,g]
//      out[b,v,q,a,g] = sum_{n,i,j,k} Tbar[i,j,k,g] v_[b,n,v,i] q_[b,n,q,j] a_[b,n,a,k]
//
// Pipeline:
//  K0:    Tbar = sum_r T[r]                        (8192-elem reduce)
//  K1-K3: vt/qt/at = relu(X @ W^T + b)             (SGEMM, N=512)
//  K4-K6: v_/q_/a_ = relu(xt @ Wxr_flat^T + b)     (SGEMM, N=512; col = n*16+c)
//  K7:    per (b,n): Tq = Tbar x_j q_, Tqa = Tq x_k a_ -> g_tqa[b][(n,i)][qag]
//  K8:    out[b] = V2[b] (100x512) @ TQA[b] (512x280)   (batched GEMM)
// ---------------------------------------------------------------------------

#define Bb    128
#define NV    100
#define NQ    14
#define NA    10
#define HDIM  512
#define RANK  32
#define HD    16
#define G     2
#define QAG   (NQ*NA*G)   // 280

// scratch (static device globals; no allocation)
__device__ float g_vt[12800 * 512];
__device__ float g_qt[1792  * 512];
__device__ float g_at[1280  * 512];
__device__ float g_v2[12800 * 512];
__device__ float g_q2[1792  * 512];
__device__ float g_a2[1280  * 512];
__device__ float g_tqa[128 * 512 * 280];
__device__ float g_Tbar[8192];

// ---------------------------------------------------------------------------
// K0: Tbar[x] = sum_r T[r*8192 + x]
// ---------------------------------------------------------------------------
__global__ void reduce_T_kernel(const float* __restrict__ T)
{
    int x = blockIdx.x * 256 + threadIdx.x;   // 0..8191
    float s = 0.f;
    #pragma unroll
    for (int r = 0; r < RANK; r++)
        s += T[(size_t)r * 8192 + x];
    g_Tbar[x] = s;
}

// ---------------------------------------------------------------------------
// SGEMM: C[m,n] = relu( sum_k A[m,k] * W[n,k] + bias[n] )
// A: [M,K] row-major, W: [N,K] row-major.
// 128x128 tile, BK=8, 256 threads, 8x8 register microtile.
// Requires M%128==0, N%128==0, K%8==0 (true for all 6 uses).
// ---------------------------------------------------------------------------
__global__ __launch_bounds__(256, 2)
void sgemm_bias_relu(const float* __restrict__ A,
                     const float* __restrict__ W,
                     const float* __restrict__ bias,
                     float* __restrict__ C,
                     int M, int N, int K)
{
    __shared__ float As[8][128];
    __shared__ float Bs[8][128];

    const int tid  = threadIdx.x;
    const int bm   = blockIdx.y * 128;
    const int bn   = blockIdx.x * 128;

    const int lrow = tid >> 1;          // 0..127
    const int lcol = (tid & 1) * 4;     // 0 or 4

    const float* Aptr = A + (size_t)(bm + lrow) * K + lcol;
    const float* Wptr = W + (size_t)(bn + lrow) * K + lcol;

    const int tx = tid & 15;            // n group
    const int ty = tid >> 4;            // m group

    float acc[8][8];
    #pragma unroll
    for (int i = 0; i < 8; i++)
        #pragma unroll
        for (int j = 0; j < 8; j++) acc[i][j] = 0.f;

    for (int k0 = 0; k0 < K; k0 += 8) {
        float4 av = *(const float4*)(Aptr + k0);
        float4 wv = *(const float4*)(Wptr + k0);
        As[lcol + 0][lrow] = av.x;
        As[lcol + 1][lrow] = av.y;
        As[lcol + 2][lrow] = av.z;
        As[lcol + 3][lrow] = av.w;
        Bs[lcol + 0][lrow] = wv.x;
        Bs[lcol + 1][lrow] = wv.y;
        Bs[lcol + 2][lrow] = wv.z;
        Bs[lcol + 3][lrow] = wv.w;
        __syncthreads();

        #pragma unroll
        for (int kk = 0; kk < 8; kk++) {
            float af[8], bf[8];
            *(float4*)&af[0] = *(const float4*)&As[kk][ty * 8];
            *(float4*)&af[4] = *(const float4*)&As[kk][ty * 8 + 4];
            *(float4*)&bf[0] = *(const float4*)&Bs[kk][tx * 8];
            *(float4*)&bf[4] = *(const float4*)&Bs[kk][tx * 8 + 4];
            #pragma unroll
            for (int i = 0; i < 8; i++)
                #pragma unroll
                for (int j = 0; j < 8; j++)
                    acc[i][j] = fmaf(af[i], bf[j], acc[i][j]);
        }
        __syncthreads();
    }

    float4 b0 = *(const float4*)(bias + bn + tx * 8);
    float4 b1 = *(const float4*)(bias + bn + tx * 8 + 4);

    #pragma unroll
    for (int i = 0; i < 8; i++) {
        float* Crow = C + (size_t)(bm + ty * 8 + i) * N + bn + tx * 8;
        float4 o0, o1;
        o0.x = fmaxf(acc[i][0] + b0.x, 0.f);
        o0.y = fmaxf(acc[i][1] + b0.y, 0.f);
        o0.z = fmaxf(acc[i][2] + b0.z, 0.f);
        o0.w = fmaxf(acc[i][3] + b0.w, 0.f);
        o1.x = fmaxf(acc[i][4] + b1.x, 0.f);
        o1.y = fmaxf(acc[i][5] + b1.y, 0.f);
        o1.z = fmaxf(acc[i][6] + b1.z, 0.f);
        o1.w = fmaxf(acc[i][7] + b1.w, 0.f);
        *(float4*)(Crow)     = o0;
        *(float4*)(Crow + 4) = o1;
    }
}

// ---------------------------------------------------------------------------
// K7: per (b,n) block:
//   Tq[q,i,k,g]  = sum_j Tbar[i,j,k,g] * q_[b,n,q,j]
//   Tqa[i,q,a,g] = sum_k Tq[q,i,k,g]   * a_[b,n,a,k]
//   write g_tqa[b][(n*16+i)][ (q*10+a)*2+g ]
// dynamic smem: 8192 (Tbar) + 224 (q) + 160 (a) + 7168 (Tq) floats = 62976 B
// ---------------------------------------------------------------------------
__global__ __launch_bounds__(256)
void tq_tqa_kernel()
{
    extern __shared__ float sm[];
    float* sT  = sm;               // 8192
    float* sQ  = sm + 8192;        // 224
    float* sA  = sm + 8416;        // 160
    float* sTq = sm + 8576;        // 7168

    const int n   = blockIdx.x;    // modality rank index
    const int b   = blockIdx.y;
    const int tid = threadIdx.x;

    // load Tbar : 8192 floats = 2048 float4 (L2-resident across all blocks)
    const float4* Tp = (const float4*)g_Tbar;
    for (int i = tid; i < 2048; i += 256) ((float4*)sT)[i] = Tp[i];

    // load q_[b,:,n,:]: 14 rows x 16 contiguous cols (= 56 float4)
    if (tid < 56) {
        int q  = tid >> 2;
        int j4 = (tid & 3) << 2;
        *(float4*)&sQ[q * 16 + j4] =
            *(const float4*)(g_q2 + (size_t)(b * NQ + q) * 512 + n * 16 + j4);
    }
    // load a_[b,:,n,:]: 10 rows x 16 cols (= 40 float4)
    if (tid >= 64 && tid < 104) {
        int t  = tid - 64;
        int a  = t >> 2;
        int k4 = (t & 3) << 2;
        *(float4*)&sA[a * 16 + k4] =
            *(const float4*)(g_a2 + (size_t)(b * NA + a) * 512 + n * 16 + k4);
    }
    __syncthreads();

    // ---- Step A: each thread owns one (i,k) pair, both g, all 14 q ----
    {
        const int i_ = tid >> 4;
        const int k_ = tid & 15;
        float accx[14], accy[14];
        #pragma unroll
        for (int q = 0; q < 14; q++) { accx[q] = 0.f; accy[q] = 0.f; }

        #pragma unroll
        for (int j = 0; j < 16; j++) {
            float2 t2 = *(const float2*)&sT[(((i_ * 16 + j) * 16) + k_) * 2];
            #pragma unroll
            for (int q = 0; q < 14; q++) {
                float qv = sQ[q * 16 + j];
                accx[q] = fmaf(t2.x, qv, accx[q]);
                accy[q] = fmaf(t2.y, qv, accy[q]);
            }
        }
        #pragma unroll
        for (int q = 0; q < 14; q++)
            *(float2*)&sTq[((q * 16 + i_) * 16 + k_) * 2] =
                make_float2(accx[q], accy[q]);
    }
    __syncthreads();

    // ---- Step B: 2240 (i,q,a) triples, each float2 over g ----
    float* out = g_tqa + ((size_t)b * 512 + n * 16) * QAG;
    for (int t = tid; t < 2240; t += 256) {
        int ii  = t / 140;
        int rem = t - ii * 140;       // q*10 + a
        int q   = rem / 10;
        int a   = rem - q * 10;
        float sx = 0.f, sy = 0.f;
        #pragma unroll
        for (int k = 0; k < 16; k++) {
            float2 tq = *(const float2*)&sTq[((q * 16 + ii) * 16 + k) * 2];
            float  av = sA[a * 16 + k];
            sx = fmaf(tq.x, av, sx);
            sy = fmaf(tq.y, av, sy);
        }
        *(float2*)&out[(size_t)ii * QAG + rem * 2] = make_float2(sx, sy);
    }
}

// ---------------------------------------------------------------------------
// K8: out[b] (100 x 280) = V2[b] (100 x 512) @ TQA[b] (512 x 280)
// grid (2, 128): col halves of 140. 256 threads; 250 active compute threads,
// each 4 v x 14 cols, K-tiles of 16 staged in smem.
// ---------------------------------------------------------------------------
__global__ __launch_bounds__(256)
void final_gemm_kernel(float* __restrict__ out)
{
    __shared__ float sV[16][100];     // [k][v]
    __shared__ float sT[16][140];     // [k][col]

    const int b   = blockIdx.y;
    const int c0  = blockIdx.x * 140;
    const int tid = threadIdx.x;

    const int tv = tid / 10;          // 0..24 (if tid<250)
    const int tc = tid - tv * 10;     // 0..9
    const bool active = (tid < 250);

    float acc[4][14];
    #pragma unroll
    for (int i = 0; i < 4; i++)
        #pragma unroll
        for (int j = 0; j < 14; j++) acc[i][j] = 0.f;

    const float* V2  = g_v2  + (size_t)b * NV  * 512;
    const float* TQA = g_tqa + (size_t)b * 512 * QAG;

    for (int kt = 0; kt < 512; kt += 16) {
        // stage V2 chunk transposed: sV[k][v]
        for (int idx = tid; idx < 1600; idx += 256) {
            int v = idx >> 4;
            int k = idx & 15;
            sV[k][v] = V2[(size_t)v * 512 + kt + k];
        }
        // stage TQA chunk: sT[k][c]
        for (int idx = tid; idx < 2240; idx += 256) {
            int k = idx / 140;
            int c = idx - k * 140;
            sT[k][c] = TQA[(size_t)(kt + k) * QAG + c0 + c];
        }
        __syncthreads();

        if (active) {
            #pragma unroll
            for (int k = 0; k < 16; k++) {
                float4 vv = *(const float4*)&sV[k][tv * 4];
                #pragma unroll
                for (int j = 0; j < 14; j++) {
                    float t = sT[k][tc * 14 + j];
                    acc[0][j] = fmaf(vv.x, t, acc[0][j]);
                    acc[1][j] = fmaf(vv.y, t, acc[1][j]);
                    acc[2][j] = fmaf(vv.z, t, acc[2][j]);
                    acc[3][j] = fmaf(vv.w, t, acc[3][j]);
                }
            }
        }
        __syncthreads();
    }

    if (active) {
        #pragma unroll
        for (int i = 0; i < 4; i++) {
            float* orow = out + (size_t)(b * NV + tv * 4 + i) * QAG + c0 + tc * 14;
            #pragma unroll
            for (int j = 0; j < 14; j++) orow[j] = acc[i][j];
        }
    }
}

// ---------------------------------------------------------------------------
extern "C" void kernel_launch(void* const* d_in, const int* in_sizes, int n_in,
                              void* d_out, int out_size)
{
    const float* v   = (const float*)d_in[0];
    const float* q   = (const float*)d_in[1];
    const float* a   = (const float*)d_in[2];
    const float* Wv  = (const float*)d_in[3];
    const float* bv  = (const float*)d_in[4];
    const float* Wq  = (const float*)d_in[5];
    const float* bq  = (const float*)d_in[6];
    const float* Wa  = (const float*)d_in[7];
    const float* ba  = (const float*)d_in[8];
    const float* Wvr = (const float*)d_in[9];
    const float* bvr = (const float*)d_in[10];
    const float* Wqr = (const float*)d_in[11];
    const float* bqr = (const float*)d_in[12];
    const float* War = (const float*)d_in[13];
    const float* bar = (const float*)d_in[14];
    const float* T   = (const float*)d_in[15];
    float* out       = (float*)d_out;

    float *p_vt, *p_qt, *p_at, *p_v2, *p_q2, *p_a2;
    cudaGetSymbolAddress((void**)&p_vt, g_vt);
    cudaGetSymbolAddress((void**)&p_qt, g_qt);
    cudaGetSymbolAddress((void**)&p_at, g_at);
    cudaGetSymbolAddress((void**)&p_v2, g_v2);
    cudaGetSymbolAddress((void**)&p_q2, g_q2);
    cudaGetSymbolAddress((void**)&p_a2, g_a2);

    cudaFuncSetAttribute(tq_tqa_kernel,
                         cudaFuncAttributeMaxDynamicSharedMemorySize, 62976);

    dim3 thr(256);

    // K0: reduce T over rank
    reduce_T_kernel<<<32, 256>>>(T);

    // stage 1: modality projections
    sgemm_bias_relu<<<dim3(4, 100), thr>>>(v, Wv, bv, p_vt, 12800, 512, 2048);
    sgemm_bias_relu<<<dim3(4, 14 ), thr>>>(q, Wq, bq, p_qt, 1792,  512, 1024);
    sgemm_bias_relu<<<dim3(4, 10 ), thr>>>(a, Wa, ba, p_at, 1280,  512, 1024);

    // stage 2: rank projections (Wxr flattened [512,512], col = n*16+c)
    sgemm_bias_relu<<<dim3(4, 100), thr>>>(p_vt, Wvr, bvr, p_v2, 12800, 512, 512);
    sgemm_bias_relu<<<dim3(4, 14 ), thr>>>(p_qt, Wqr, bqr, p_q2, 1792,  512, 512);
    sgemm_bias_relu<<<dim3(4, 10 ), thr>>>(p_at, War, bar, p_a2, 1280,  512, 512);

    // stage 3: Tucker core contraction with q_ and a_
    tq_tqa_kernel<<<dim3(RANK, Bb), thr, 62976>>>();

    // stage 4: batched final GEMM -> output
    final_gemm_kernel<<<dim3(2, Bb), thr>>>(out);
}

// round 4
// speedup vs baseline: 2.1385x; 2.1385x over previous
#include <cuda_runtime.h>
#include <cuda_bf16.h>
#include <cstdint>

// ---------------------------------------------------------------------------
// TCNet: B=128, NV=100, NQ=14, NA=10, V_DIM=2048, Q_DIM=1024, A_DIM=1024,
//        H_DIM=512, RANK=32, HD=16, G=2
//
// einsum 'rijkg,bnvi,bnqj,bnak->bvqag' : r and n are INDEPENDENT sums.
//   Tbar[i,j,k,g] = sum_r T[r,i,j,k,g]
//   out[b,v,q,a,g] = sum_{n,i,j,k} Tbar v_ q_ a_
//
// GEMMs: warp-level mma.sync bf16 (HMMA), bf16x3 fp32 emulation
// (hi*hi + hi*lo + lo*hi). tcgen05 is NOT available (ptxas targets sm_103
// without the 'a' feature suffix), so we use the baseline tensor path.
// ---------------------------------------------------------------------------

#define Bb    128
#define NV    100
#define NQ    14
#define NA    10
#define RANK  32
#define G     2
#define QAG   (NQ*NA*G)   // 280

// ---------------- scratch (static device globals) ----------------
__device__ __align__(256) __nv_bfloat16 g_v_hi [12800*2048], g_v_lo [12800*2048];
__device__ __align__(256) __nv_bfloat16 g_q_hi [1792*1024],  g_q_lo [1792*1024];
__device__ __align__(256) __nv_bfloat16 g_a_hi [1280*1024],  g_a_lo [1280*1024];
__device__ __align__(256) __nv_bfloat16 g_Wv_hi[512*2048],   g_Wv_lo[512*2048];
__device__ __align__(256) __nv_bfloat16 g_Wq_hi[512*1024],   g_Wq_lo[512*1024];
__device__ __align__(256) __nv_bfloat16 g_Wa_hi[512*1024],   g_Wa_lo[512*1024];
__device__ __align__(256) __nv_bfloat16 g_Wvr_hi[512*512],   g_Wvr_lo[512*512];
__device__ __align__(256) __nv_bfloat16 g_Wqr_hi[512*512],   g_Wqr_lo[512*512];
__device__ __align__(256) __nv_bfloat16 g_War_hi[512*512],   g_War_lo[512*512];
__device__ __align__(256) __nv_bfloat16 g_vt_hi[12800*512],  g_vt_lo[12800*512];
__device__ __align__(256) __nv_bfloat16 g_qt_hi[1792*512],   g_qt_lo[1792*512];
__device__ __align__(256) __nv_bfloat16 g_at_hi[1280*512],   g_at_lo[1280*512];
__device__ __align__(256) float g_v2[12800*512];
__device__ __align__(256) float g_q2[1792*512];
__device__ __align__(256) float g_a2[1280*512];
__device__ __align__(256) float g_tqa[128*512*280];
__device__ __align__(256) float g_Tbar[8192];

// ---------------- PTX helpers ----------------
__device__ __forceinline__ uint32_t smem_u32(const void* p) {
    uint32_t a;
    asm("{ .reg .u64 t; cvta.to.shared.u64 t, %1; cvt.u32.u64 %0, t; }"
        : "=r"(a) : "l"(p));
    return a;
}
__device__ __forceinline__ void mma_bf16(float* c, const uint32_t* a,
                                         const uint32_t* b) {
    asm volatile(
        "mma.sync.aligned.m16n8k16.row.col.f32.bf16.bf16.f32 "
        "{%0,%1,%2,%3}, {%4,%5,%6,%7}, {%8,%9}, {%0,%1,%2,%3};"
        : "+f"(c[0]), "+f"(c[1]), "+f"(c[2]), "+f"(c[3])
        : "r"(a[0]), "r"(a[1]), "r"(a[2]), "r"(a[3]), "r"(b[0]), "r"(b[1]));
}
__device__ __forceinline__ void ldsm4(uint32_t* r, uint32_t addr) {
    asm volatile("ldmatrix.sync.aligned.m8n8.x4.shared.b16 {%0,%1,%2,%3}, [%4];"
                 : "=r"(r[0]), "=r"(r[1]), "=r"(r[2]), "=r"(r[3]) : "r"(addr));
}
__device__ __forceinline__ void cp16(uint32_t dst, const void* src) {
    asm volatile("cp.async.cg.shared.global [%0], [%1], 16;"
                 :: "r"(dst), "l"(src));
}
__device__ __forceinline__ void cp_commit() {
    asm volatile("cp.async.commit_group;");
}
template<int N>
__device__ __forceinline__ void cp_wait() {
    asm volatile("cp.async.wait_group %0;" :: "n"(N));
}

// ---------------------------------------------------------------------------
// K-pre: split fp32 -> bf16 hi/lo
// ---------------------------------------------------------------------------
__global__ void split_bf16_kernel(const float* __restrict__ x,
                                  __nv_bfloat16* __restrict__ hi,
                                  __nv_bfloat16* __restrict__ lo, int n4)
{
    int i = blockIdx.x * 256 + threadIdx.x;
    if (i >= n4) return;
    float4 v = ((const float4*)x)[i];
    __nv_bfloat16 h0 = __float2bfloat16(v.x), h1 = __float2bfloat16(v.y);
    __nv_bfloat16 h2 = __float2bfloat16(v.z), h3 = __float2bfloat16(v.w);
    __nv_bfloat162 H0 = {h0, h1}, H1 = {h2, h3};
    __nv_bfloat162 L0 = {__float2bfloat16(v.x - __bfloat162float(h0)),
                         __float2bfloat16(v.y - __bfloat162float(h1))};
    __nv_bfloat162 L1 = {__float2bfloat16(v.z - __bfloat162float(h2)),
                         __float2bfloat16(v.w - __bfloat162float(h3))};
    ((__nv_bfloat162*)hi)[i*2]   = H0;
    ((__nv_bfloat162*)hi)[i*2+1] = H1;
    ((__nv_bfloat162*)lo)[i*2]   = L0;
    ((__nv_bfloat162*)lo)[i*2+1] = L1;
}

// ---------------------------------------------------------------------------
// K0: Tbar[x] = sum_r T[r*8192 + x]
// ---------------------------------------------------------------------------
__global__ void reduce_T_kernel(const float* __restrict__ T)
{
    int x = blockIdx.x * 256 + threadIdx.x;
    float s = 0.f;
    #pragma unroll
    for (int r = 0; r < RANK; r++) s += T[(size_t)r * 8192 + x];
    g_Tbar[x] = s;
}

// ---------------------------------------------------------------------------
// HMMA bf16x3 GEMM: C[m,n] = relu( sum_k A[m,k]*W[n,k] + bias[n] )
// BM=128, BN=128, BK=32, 256 threads (8 warps, warp tile 32x64),
// cp.async double buffer, XOR-swizzled 64B smem rows (conflict-free ldmatrix).
// ---------------------------------------------------------------------------
#define STAGE_SZ 32768                 // 4 x 8192B regions per stage
#define GEMM_SMEM (2 * STAGE_SZ)       // 65536

// smem offsets within a stage
#define OFF_AH 0
#define OFF_AL 8192
#define OFF_BH 16384
#define OFF_BL 24576

__device__ __forceinline__ uint32_t swz_off(int row, int c) {
    return (uint32_t)(row * 64 + ((c ^ ((row >> 1) & 3)) << 4));
}

template<int OUT_BF16>
__global__ __launch_bounds__(256, 1)
void mma_gemm(const __nv_bfloat16* __restrict__ Ahi,
              const __nv_bfloat16* __restrict__ Alo,
              const __nv_bfloat16* __restrict__ Bhi,
              const __nv_bfloat16* __restrict__ Blo,
              const float* __restrict__ bias,
              float* __restrict__ Cf,
              __nv_bfloat16* __restrict__ Chi,
              __nv_bfloat16* __restrict__ Clo,
              int M, int N, int K)
{
    extern __shared__ char smem[];
    const uint32_t smb = smem_u32(smem);
    const int tid  = threadIdx.x;
    const int wid  = tid >> 5;
    const int lane = tid & 31;
    const int wm   = wid & 3;          // 4 warps along M (32 rows each)
    const int wn   = wid >> 2;         // 2 warps along N (64 cols each)
    const int bm   = blockIdx.y * 128;
    const int bn   = blockIdx.x * 128;

    const int nchunks = K >> 5;        // BK = 32

    // ---- stage loader (cp.async) ----
    auto load_stage = [&](int c) {
        const uint32_t sb = smb + (uint32_t)(c & 1) * STAGE_SZ;
        const int k0 = c << 5;
        #pragma unroll
        for (int i = 0; i < 2; i++) {
            int idx = tid + i * 256;         // 0..511
            int row = idx >> 2;
            int cc  = idx & 3;
            uint32_t so = swz_off(row, cc);
            size_t gA = (size_t)(bm + row) * K + k0 + cc * 8;
            size_t gB = (size_t)(bn + row) * K + k0 + cc * 8;
            cp16(sb + OFF_AH + so, Ahi + gA);
            cp16(sb + OFF_AL + so, Alo + gA);
            cp16(sb + OFF_BH + so, Bhi + gB);
            cp16(sb + OFF_BL + so, Blo + gB);
        }
    };

    float acc[2][8][4];
    #pragma unroll
    for (int mt = 0; mt < 2; mt++)
        #pragma unroll
        for (int nt = 0; nt < 8; nt++)
            #pragma unroll
            for (int i = 0; i < 4; i++) acc[mt][nt][i] = 0.f;

    // ldmatrix lane addressing (within tile)
    const int a_r = (lane & 7) | (((lane >> 3) & 1) << 3);  // row 0..15
    const int a_c = lane >> 4;                              // k8 chunk 0..1
    const int b_r = (lane & 7) | ((lane >> 4) << 3);
    const int b_c = (lane >> 3) & 1;

    load_stage(0);
    cp_commit();

    for (int c = 0; c < nchunks; c++) {
        if (c + 1 < nchunks) {
            load_stage(c + 1);
            cp_commit();
            cp_wait<1>();
        } else {
            cp_wait<0>();
        }
        __syncthreads();

        const uint32_t sb = smb + (uint32_t)(c & 1) * STAGE_SZ;

        #pragma unroll
        for (int ks8 = 0; ks8 < 4; ks8 += 2) {   // ks = ks8*8 in {0,16}
            uint32_t af_h[2][4], af_l[2][4];
            #pragma unroll
            for (int mt = 0; mt < 2; mt++) {
                int row = wm * 32 + mt * 16 + a_r;
                uint32_t so = swz_off(row, ks8 + a_c);
                ldsm4(af_h[mt], sb + OFF_AH + so);
                ldsm4(af_l[mt], sb + OFF_AL + so);
            }
            uint32_t bf_h[4][4], bf_l[4][4];
            #pragma unroll
            for (int nq = 0; nq < 4; nq++) {
                int row = wn * 64 + nq * 16 + b_r;
                uint32_t so = swz_off(row, ks8 + b_c);
                ldsm4(bf_h[nq], sb + OFF_BH + so);
                ldsm4(bf_l[nq], sb + OFF_BL + so);
            }
            #pragma unroll
            for (int mt = 0; mt < 2; mt++)
                #pragma unroll
                for (int nt = 0; nt < 8; nt++) {
                    const uint32_t* bh = &bf_h[nt >> 1][(nt & 1) * 2];
                    const uint32_t* bl = &bf_l[nt >> 1][(nt & 1) * 2];
                    mma_bf16(acc[mt][nt], af_h[mt], bh);
                    mma_bf16(acc[mt][nt], af_h[mt], bl);
                    mma_bf16(acc[mt][nt], af_l[mt], bh);
                }
        }
        __syncthreads();
    }

    // ---- epilogue: bias + relu ----
    const int g = lane >> 2;
    const int t = lane & 3;
    #pragma unroll
    for (int mt = 0; mt < 2; mt++) {
        #pragma unroll
        for (int nt = 0; nt < 8; nt++) {
            int row0 = bm + wm * 32 + mt * 16 + g;
            int row1 = row0 + 8;
            int col  = bn + wn * 64 + nt * 8 + t * 2;
            float bs0 = __ldg(bias + col), bs1 = __ldg(bias + col + 1);
            float v00 = fmaxf(acc[mt][nt][0] + bs0, 0.f);
            float v01 = fmaxf(acc[mt][nt][1] + bs1, 0.f);
            float v10 = fmaxf(acc[mt][nt][2] + bs0, 0.f);
            float v11 = fmaxf(acc[mt][nt][3] + bs1, 0.f);
            if (OUT_BF16) {
                __nv_bfloat16 h00 = __float2bfloat16(v00);
                __nv_bfloat16 h01 = __float2bfloat16(v01);
                __nv_bfloat16 h10 = __float2bfloat16(v10);
                __nv_bfloat16 h11 = __float2bfloat16(v11);
                __nv_bfloat162 H0 = {h00, h01}, H1 = {h10, h11};
                __nv_bfloat162 L0 = {
                    __float2bfloat16(v00 - __bfloat162float(h00)),
                    __float2bfloat16(v01 - __bfloat162float(h01))};
                __nv_bfloat162 L1 = {
                    __float2bfloat16(v10 - __bfloat162float(h10)),
                    __float2bfloat16(v11 - __bfloat162float(h11))};
                *(__nv_bfloat162*)(Chi + (size_t)row0 * N + col) = H0;
                *(__nv_bfloat162*)(Clo + (size_t)row0 * N + col) = L0;
                *(__nv_bfloat162*)(Chi + (size_t)row1 * N + col) = H1;
                *(__nv_bfloat162*)(Clo + (size_t)row1 * N + col) = L1;
            } else {
                *(float2*)(Cf + (size_t)row0 * N + col) = make_float2(v00, v01);
                *(float2*)(Cf + (size_t)row1 * N + col) = make_float2(v10, v11);
            }
        }
    }
}

// ---------------------------------------------------------------------------
// K7: per (b,n):  Tq = Tbar x_j q_,  Tqa = Tq x_k a_  -> g_tqa
// ---------------------------------------------------------------------------
__global__ __launch_bounds__(256)
void tq_tqa_kernel()
{
    extern __shared__ float sm[];
    float* sT  = sm;               // 8192
    float* sQ  = sm + 8192;        // 224
    float* sA  = sm + 8416;        // 160
    float* sTq = sm + 8576;        // 7168

    const int n   = blockIdx.x;
    const int b   = blockIdx.y;
    const int tid = threadIdx.x;

    const float4* Tp = (const float4*)g_Tbar;
    for (int i = tid; i < 2048; i += 256) ((float4*)sT)[i] = Tp[i];

    if (tid < 56) {
        int q  = tid >> 2;
        int j4 = (tid & 3) << 2;
        *(float4*)&sQ[q * 16 + j4] =
            *(const float4*)(g_q2 + (size_t)(b * NQ + q) * 512 + n * 16 + j4);
    }
    if (tid >= 64 && tid < 104) {
        int t  = tid - 64;
        int a  = t >> 2;
        int k4 = (t & 3) << 2;
        *(float4*)&sA[a * 16 + k4] =
            *(const float4*)(g_a2 + (size_t)(b * NA + a) * 512 + n * 16 + k4);
    }
    __syncthreads();

    {
        const int i_ = tid >> 4;
        const int k_ = tid & 15;
        float accx[14], accy[14];
        #pragma unroll
        for (int q = 0; q < 14; q++) { accx[q] = 0.f; accy[q] = 0.f; }
        #pragma unroll
        for (int j = 0; j < 16; j++) {
            float2 t2 = *(const float2*)&sT[(((i_ * 16 + j) * 16) + k_) * 2];
            #pragma unroll
            for (int q = 0; q < 14; q++) {
                float qv = sQ[q * 16 + j];
                accx[q] = fmaf(t2.x, qv, accx[q]);
                accy[q] = fmaf(t2.y, qv, accy[q]);
            }
        }
        #pragma unroll
        for (int q = 0; q < 14; q++)
            *(float2*)&sTq[((q * 16 + i_) * 16 + k_) * 2] =
                make_float2(accx[q], accy[q]);
    }
    __syncthreads();

    float* out = g_tqa + ((size_t)b * 512 + n * 16) * QAG;
    for (int t = tid; t < 2240; t += 256) {
        int ii  = t / 140;
        int rem = t - ii * 140;
        int q   = rem / 10;
        int a   = rem - q * 10;
        float sx = 0.f, sy = 0.f;
        #pragma unroll
        for (int k = 0; k < 16; k++) {
            float2 tq = *(const float2*)&sTq[((q * 16 + ii) * 16 + k) * 2];
            float  av = sA[a * 16 + k];
            sx = fmaf(tq.x, av, sx);
            sy = fmaf(tq.y, av, sy);
        }
        *(float2*)&out[(size_t)ii * QAG + rem * 2] = make_float2(sx, sy);
    }
}

// ---------------------------------------------------------------------------
// K8: out[b] (100x280) = V2[b] (100x512) @ TQA[b] (512x280)
// ---------------------------------------------------------------------------
__global__ __launch_bounds__(256)
void final_gemm_kernel(float* __restrict__ out)
{
    __shared__ float sV[16][100];
    __shared__ float sT[16][140];

    const int b   = blockIdx.y;
    const int c0  = blockIdx.x * 140;
    const int tid = threadIdx.x;

    const int tv = tid / 10;
    const int tc = tid - tv * 10;
    const bool active = (tid < 250);

    float acc[4][14];
    #pragma unroll
    for (int i = 0; i < 4; i++)
        #pragma unroll
        for (int j = 0; j < 14; j++) acc[i][j] = 0.f;

    const float* V2  = g_v2  + (size_t)b * NV  * 512;
    const float* TQA = g_tqa + (size_t)b * 512 * QAG;

    for (int kt = 0; kt < 512; kt += 16) {
        for (int idx = tid; idx < 1600; idx += 256) {
            int v = idx >> 4;
            int k = idx & 15;
            sV[k][v] = V2[(size_t)v * 512 + kt + k];
        }
        for (int idx = tid; idx < 2240; idx += 256) {
            int k = idx / 140;
            int c = idx - k * 140;
            sT[k][c] = TQA[(size_t)(kt + k) * QAG + c0 + c];
        }
        __syncthreads();

        if (active) {
            #pragma unroll
            for (int k = 0; k < 16; k++) {
                float4 vv = *(const float4*)&sV[k][tv * 4];
                #pragma unroll
                for (int j = 0; j < 14; j++) {
                    float t = sT[k][tc * 14 + j];
                    acc[0][j] = fmaf(vv.x, t, acc[0][j]);
                    acc[1][j] = fmaf(vv.y, t, acc[1][j]);
                    acc[2][j] = fmaf(vv.z, t, acc[2][j]);
                    acc[3][j] = fmaf(vv.w, t, acc[3][j]);
                }
            }
        }
        __syncthreads();
    }

    if (active) {
        #pragma unroll
        for (int i = 0; i < 4; i++) {
            float* orow = out + (size_t)(b * NV + tv * 4 + i) * QAG + c0 + tc * 14;
            #pragma unroll
            for (int j = 0; j < 14; j++) orow[j] = acc[i][j];
        }
    }
}

// ---------------------------------------------------------------------------
extern "C" void kernel_launch(void* const* d_in, const int* in_sizes, int n_in,
                              void* d_out, int out_size)
{
    const float* v   = (const float*)d_in[0];
    const float* q   = (const float*)d_in[1];
    const float* a   = (const float*)d_in[2];
    const float* Wv  = (const float*)d_in[3];
    const float* bv  = (const float*)d_in[4];
    const float* Wq  = (const float*)d_in[5];
    const float* bq  = (const float*)d_in[6];
    const float* Wa  = (const float*)d_in[7];
    const float* ba  = (const float*)d_in[8];
    const float* Wvr = (const float*)d_in[9];
    const float* bvr = (const float*)d_in[10];
    const float* Wqr = (const float*)d_in[11];
    const float* bqr = (const float*)d_in[12];
    const float* War = (const float*)d_in[13];
    const float* bar = (const float*)d_in[14];
    const float* T   = (const float*)d_in[15];
    float* out       = (float*)d_out;

    __nv_bfloat16 *vhi,*vlo,*qhi,*qlo,*ahi,*alo;
    __nv_bfloat16 *Wvhi,*Wvlo,*Wqhi,*Wqlo,*Wahi,*Walo;
    __nv_bfloat16 *Wvrhi,*Wvrlo,*Wqrhi,*Wqrlo,*Warhi,*Warlo;
    __nv_bfloat16 *vthi,*vtlo,*qthi,*qtlo,*athi,*atlo;
    float *pv2,*pq2,*pa2;
    cudaGetSymbolAddress((void**)&vhi, g_v_hi);   cudaGetSymbolAddress((void**)&vlo, g_v_lo);
    cudaGetSymbolAddress((void**)&qhi, g_q_hi);   cudaGetSymbolAddress((void**)&qlo, g_q_lo);
    cudaGetSymbolAddress((void**)&ahi, g_a_hi);   cudaGetSymbolAddress((void**)&alo, g_a_lo);
    cudaGetSymbolAddress((void**)&Wvhi, g_Wv_hi); cudaGetSymbolAddress((void**)&Wvlo, g_Wv_lo);
    cudaGetSymbolAddress((void**)&Wqhi, g_Wq_hi); cudaGetSymbolAddress((void**)&Wqlo, g_Wq_lo);
    cudaGetSymbolAddress((void**)&Wahi, g_Wa_hi); cudaGetSymbolAddress((void**)&Walo, g_Wa_lo);
    cudaGetSymbolAddress((void**)&Wvrhi, g_Wvr_hi); cudaGetSymbolAddress((void**)&Wvrlo, g_Wvr_lo);
    cudaGetSymbolAddress((void**)&Wqrhi, g_Wqr_hi); cudaGetSymbolAddress((void**)&Wqrlo, g_Wqr_lo);
    cudaGetSymbolAddress((void**)&Warhi, g_War_hi); cudaGetSymbolAddress((void**)&Warlo, g_War_lo);
    cudaGetSymbolAddress((void**)&vthi, g_vt_hi); cudaGetSymbolAddress((void**)&vtlo, g_vt_lo);
    cudaGetSymbolAddress((void**)&qthi, g_qt_hi); cudaGetSymbolAddress((void**)&qtlo, g_qt_lo);
    cudaGetSymbolAddress((void**)&athi, g_at_hi); cudaGetSymbolAddress((void**)&atlo, g_at_lo);
    cudaGetSymbolAddress((void**)&pv2, g_v2);
    cudaGetSymbolAddress((void**)&pq2, g_q2);
    cudaGetSymbolAddress((void**)&pa2, g_a2);

    cudaFuncSetAttribute(mma_gemm<0>, cudaFuncAttributeMaxDynamicSharedMemorySize, GEMM_SMEM);
    cudaFuncSetAttribute(mma_gemm<1>, cudaFuncAttributeMaxDynamicSharedMemorySize, GEMM_SMEM);
    cudaFuncSetAttribute(tq_tqa_kernel, cudaFuncAttributeMaxDynamicSharedMemorySize, 62976);

    dim3 thr(256);

    auto split = [&](const float* x, __nv_bfloat16* h, __nv_bfloat16* l, int n) {
        int n4 = n / 4;
        split_bf16_kernel<<<(n4 + 255) / 256, 256>>>(x, h, l, n4);
    };
    split(v,   vhi,   vlo,   12800 * 2048);
    split(q,   qhi,   qlo,   1792  * 1024);
    split(a,   ahi,   alo,   1280  * 1024);
    split(Wv,  Wvhi,  Wvlo,  512 * 2048);
    split(Wq,  Wqhi,  Wqlo,  512 * 1024);
    split(Wa,  Wahi,  Walo,  512 * 1024);
    split(Wvr, Wvrhi, Wvrlo, 512 * 512);
    split(Wqr, Wqrhi, Wqrlo, 512 * 512);
    split(War, Warhi, Warlo, 512 * 512);

    reduce_T_kernel<<<32, 256>>>(T);

    // stage 1: modality projections (bf16 hi/lo out)
    mma_gemm<1><<<dim3(4,100), thr, GEMM_SMEM>>>(vhi, vlo, Wvhi, Wvlo, bv,
                                                 nullptr, vthi, vtlo, 12800, 512, 2048);
    mma_gemm<1><<<dim3(4,14),  thr, GEMM_SMEM>>>(qhi, qlo, Wqhi, Wqlo, bq,
                                                 nullptr, qthi, qtlo, 1792, 512, 1024);
    mma_gemm<1><<<dim3(4,10),  thr, GEMM_SMEM>>>(ahi, alo, Wahi, Walo, ba,
                                                 nullptr, athi, atlo, 1280, 512, 1024);

    // stage 2: rank projections (fp32 out)
    mma_gemm<0><<<dim3(4,100), thr, GEMM_SMEM>>>(vthi, vtlo, Wvrhi, Wvrlo, bvr,
                                                 pv2, nullptr, nullptr, 12800, 512, 512);
    mma_gemm<0><<<dim3(4,14),  thr, GEMM_SMEM>>>(qthi, qtlo, Wqrhi, Wqrlo, bqr,
                                                 pq2, nullptr, nullptr, 1792, 512, 512);
    mma_gemm<0><<<dim3(4,10),  thr, GEMM_SMEM>>>(athi, atlo, Warhi, Warlo, bar,
                                                 pa2, nullptr, nullptr, 1280, 512, 512);

    // stage 3: Tucker core contraction
    tq_tqa_kernel<<<dim3(RANK, Bb), thr, 62976>>>();

    // stage 4: final batched GEMM -> output
    final_gemm_kernel<<<dim3(2, Bb), thr>>>(out);
}

// round 5
// speedup vs baseline: 2.6489x; 1.2387x over previous
#include <cuda_runtime.h>
#include <cuda_bf16.h>
#include <cstdint>

// ---------------------------------------------------------------------------
// TCNet: B=128, NV=100, NQ=14, NA=10, V_DIM=2048, Q_DIM=1024, A_DIM=1024,
//        H_DIM=512, RANK=32, HD=16, G=2
//
// einsum 'rijkg,bnvi,bnqj,bnak->bvqag' : r and n are INDEPENDENT sums.
//   Tbar[i,j,k,g] = sum_r T[r,i,j,k,g]
//   out[b,v,q,a,g] = sum_{n,i,j,k} Tbar v_ q_ a_
//
// All big GEMMs (stages 1,2 and the final batched GEMM) run on mma.sync bf16
// (HMMA) with bf16x3 fp32 emulation: hi*hi + hi*lo + lo*hi.
// ---------------------------------------------------------------------------

#define Bb    128
#define NV    100
#define NQ    14
#define NA    10
#define RANK  32
#define G     2
#define QAG   (NQ*NA*G)   // 280
#define CPAD  288         // padded TQA_T row count

// ---------------- scratch (static device globals, zero-initialized) --------
__device__ __align__(256) __nv_bfloat16 g_v_hi [12800*2048], g_v_lo [12800*2048];
__device__ __align__(256) __nv_bfloat16 g_q_hi [1792*1024],  g_q_lo [1792*1024];
__device__ __align__(256) __nv_bfloat16 g_a_hi [1280*1024],  g_a_lo [1280*1024];
__device__ __align__(256) __nv_bfloat16 g_Wv_hi[512*2048],   g_Wv_lo[512*2048];
__device__ __align__(256) __nv_bfloat16 g_Wq_hi[512*1024],   g_Wq_lo[512*1024];
__device__ __align__(256) __nv_bfloat16 g_Wa_hi[512*1024],   g_Wa_lo[512*1024];
__device__ __align__(256) __nv_bfloat16 g_Wvr_hi[512*512],   g_Wvr_lo[512*512];
__device__ __align__(256) __nv_bfloat16 g_Wqr_hi[512*512],   g_Wqr_lo[512*512];
__device__ __align__(256) __nv_bfloat16 g_War_hi[512*512],   g_War_lo[512*512];
__device__ __align__(256) __nv_bfloat16 g_vt_hi[12800*512],  g_vt_lo[12800*512];
__device__ __align__(256) __nv_bfloat16 g_qt_hi[1792*512],   g_qt_lo[1792*512];
__device__ __align__(256) __nv_bfloat16 g_at_hi[1280*512],   g_at_lo[1280*512];
// stage-2 v output, bf16 hi/lo (padded +32 rows: K8 reads 128-row tiles)
__device__ __align__(256) __nv_bfloat16 g_v2_hi[12832*512],  g_v2_lo[12832*512];
__device__ __align__(256) float g_q2[1792*512];
__device__ __align__(256) float g_a2[1280*512];
// TQA transposed: [b][c(288)][k(512)], bf16 hi/lo; rows 280..287 stay zero
__device__ __align__(256) __nv_bfloat16 g_tqaT_hi[128*CPAD*512];
__device__ __align__(256) __nv_bfloat16 g_tqaT_lo[128*CPAD*512];
__device__ __align__(256) float g_Tbar[8192];

// ---------------- PTX helpers ----------------
__device__ __forceinline__ uint32_t smem_u32(const void* p) {
    uint32_t a;
    asm("{ .reg .u64 t; cvta.to.shared.u64 t, %1; cvt.u32.u64 %0, t; }"
        : "=r"(a) : "l"(p));
    return a;
}
__device__ __forceinline__ void mma_bf16(float* c, const uint32_t* a,
                                         const uint32_t* b) {
    asm volatile(
        "mma.sync.aligned.m16n8k16.row.col.f32.bf16.bf16.f32 "
        "{%0,%1,%2,%3}, {%4,%5,%6,%7}, {%8,%9}, {%0,%1,%2,%3};"
        : "+f"(c[0]), "+f"(c[1]), "+f"(c[2]), "+f"(c[3])
        : "r"(a[0]), "r"(a[1]), "r"(a[2]), "r"(a[3]), "r"(b[0]), "r"(b[1]));
}
__device__ __forceinline__ void ldsm4(uint32_t* r, uint32_t addr) {
    asm volatile("ldmatrix.sync.aligned.m8n8.x4.shared.b16 {%0,%1,%2,%3}, [%4];"
                 : "=r"(r[0]), "=r"(r[1]), "=r"(r[2]), "=r"(r[3]) : "r"(addr));
}
__device__ __forceinline__ void cp16(uint32_t dst, const void* src) {
    asm volatile("cp.async.cg.shared.global [%0], [%1], 16;"
                 :: "r"(dst), "l"(src));
}
__device__ __forceinline__ void cp_commit() {
    asm volatile("cp.async.commit_group;");
}
template<int N>
__device__ __forceinline__ void cp_wait() {
    asm volatile("cp.async.wait_group %0;" :: "n"(N));
}
__device__ __forceinline__ uint32_t swz_off(int row, int c) {
    return (uint32_t)(row * 64 + ((c ^ ((row >> 1) & 3)) << 4));
}

// ---------------------------------------------------------------------------
// split fp32 -> bf16 hi/lo
// ---------------------------------------------------------------------------
__global__ void split_bf16_kernel(const float* __restrict__ x,
                                  __nv_bfloat16* __restrict__ hi,
                                  __nv_bfloat16* __restrict__ lo, int n4)
{
    int i = blockIdx.x * 256 + threadIdx.x;
    if (i >= n4) return;
    float4 v = ((const float4*)x)[i];
    __nv_bfloat16 h0 = __float2bfloat16(v.x), h1 = __float2bfloat16(v.y);
    __nv_bfloat16 h2 = __float2bfloat16(v.z), h3 = __float2bfloat16(v.w);
    __nv_bfloat162 H0 = {h0, h1}, H1 = {h2, h3};
    __nv_bfloat162 L0 = {__float2bfloat16(v.x - __bfloat162float(h0)),
                         __float2bfloat16(v.y - __bfloat162float(h1))};
    __nv_bfloat162 L1 = {__float2bfloat16(v.z - __bfloat162float(h2)),
                         __float2bfloat16(v.w - __bfloat162float(h3))};
    ((__nv_bfloat162*)hi)[i*2]   = H0;
    ((__nv_bfloat162*)hi)[i*2+1] = H1;
    ((__nv_bfloat162*)lo)[i*2]   = L0;
    ((__nv_bfloat162*)lo)[i*2+1] = L1;
}

// ---------------------------------------------------------------------------
// Tbar[x] = sum_r T[r*8192 + x]
// ---------------------------------------------------------------------------
__global__ void reduce_T_kernel(const float* __restrict__ T)
{
    int x = blockIdx.x * 256 + threadIdx.x;
    float s = 0.f;
    #pragma unroll
    for (int r = 0; r < RANK; r++) s += T[(size_t)r * 8192 + x];
    g_Tbar[x] = s;
}

// ---------------------------------------------------------------------------
// HMMA bf16x3 GEMM: C[m,n] = relu( sum_k A[m,k]*W[n,k] + bias[n] )
// BM=128, BN=128, BK=32, 512 threads (16 warps 4x4, warp tile 32x32),
// cp.async double buffer, XOR-swizzled 64B rows.
// ---------------------------------------------------------------------------
#define STAGE_SZ 32768
#define GEMM_SMEM (2 * STAGE_SZ)
#define OFF_AH 0
#define OFF_AL 8192
#define OFF_BH 16384
#define OFF_BL 24576

template<int OUT_BF16>
__global__ __launch_bounds__(512, 1)
void mma_gemm(const __nv_bfloat16* __restrict__ Ahi,
              const __nv_bfloat16* __restrict__ Alo,
              const __nv_bfloat16* __restrict__ Bhi,
              const __nv_bfloat16* __restrict__ Blo,
              const float* __restrict__ bias,
              float* __restrict__ Cf,
              __nv_bfloat16* __restrict__ Chi,
              __nv_bfloat16* __restrict__ Clo,
              int M, int N, int K)
{
    extern __shared__ char smem[];
    const uint32_t smb = smem_u32(smem);
    const int tid  = threadIdx.x;
    const int wid  = tid >> 5;
    const int lane = tid & 31;
    const int wm   = wid & 3;          // 4 warps along M (32 rows)
    const int wn   = wid >> 2;         // 4 warps along N (32 cols)
    const int bm   = blockIdx.y * 128;
    const int bn   = blockIdx.x * 128;

    const int nchunks = K >> 5;

    const int l_row = tid >> 2;        // 0..127
    const int l_cc  = tid & 3;
    const uint32_t l_so = swz_off(l_row, l_cc);

    auto load_stage = [&](int c) {
        const uint32_t sb = smb + (uint32_t)(c & 1) * STAGE_SZ;
        const int k0 = c << 5;
        size_t gA = (size_t)(bm + l_row) * K + k0 + l_cc * 8;
        size_t gB = (size_t)(bn + l_row) * K + k0 + l_cc * 8;
        cp16(sb + OFF_AH + l_so, Ahi + gA);
        cp16(sb + OFF_AL + l_so, Alo + gA);
        cp16(sb + OFF_BH + l_so, Bhi + gB);
        cp16(sb + OFF_BL + l_so, Blo + gB);
    };

    float acc[2][4][4];
    #pragma unroll
    for (int mt = 0; mt < 2; mt++)
        #pragma unroll
        for (int nt = 0; nt < 4; nt++)
            #pragma unroll
            for (int i = 0; i < 4; i++) acc[mt][nt][i] = 0.f;

    const int a_r = (lane & 7) | (((lane >> 3) & 1) << 3);
    const int a_c = lane >> 4;
    const int b_r = (lane & 7) | ((lane >> 4) << 3);
    const int b_c = (lane >> 3) & 1;

    load_stage(0);
    cp_commit();

    for (int c = 0; c < nchunks; c++) {
        if (c + 1 < nchunks) {
            load_stage(c + 1);
            cp_commit();
            cp_wait<1>();
        } else {
            cp_wait<0>();
        }
        __syncthreads();

        const uint32_t sb = smb + (uint32_t)(c & 1) * STAGE_SZ;

        #pragma unroll
        for (int ks8 = 0; ks8 < 4; ks8 += 2) {
            uint32_t af_h[2][4], af_l[2][4];
            #pragma unroll
            for (int mt = 0; mt < 2; mt++) {
                int row = wm * 32 + mt * 16 + a_r;
                uint32_t so = swz_off(row, ks8 + a_c);
                ldsm4(af_h[mt], sb + OFF_AH + so);
                ldsm4(af_l[mt], sb + OFF_AL + so);
            }
            uint32_t bf_h[2][4], bf_l[2][4];
            #pragma unroll
            for (int nq = 0; nq < 2; nq++) {
                int row = wn * 32 + nq * 16 + b_r;
                uint32_t so = swz_off(row, ks8 + b_c);
                ldsm4(bf_h[nq], sb + OFF_BH + so);
                ldsm4(bf_l[nq], sb + OFF_BL + so);
            }
            #pragma unroll
            for (int mt = 0; mt < 2; mt++)
                #pragma unroll
                for (int nt = 0; nt < 4; nt++) {
                    const uint32_t* bh = &bf_h[nt >> 1][(nt & 1) * 2];
                    const uint32_t* bl = &bf_l[nt >> 1][(nt & 1) * 2];
                    mma_bf16(acc[mt][nt], af_h[mt], bh);
                    mma_bf16(acc[mt][nt], af_h[mt], bl);
                    mma_bf16(acc[mt][nt], af_l[mt], bh);
                }
        }
        __syncthreads();
    }

    // epilogue: bias + relu
    const int g = lane >> 2;
    const int t = lane & 3;
    #pragma unroll
    for (int mt = 0; mt < 2; mt++) {
        #pragma unroll
        for (int nt = 0; nt < 4; nt++) {
            int row0 = bm + wm * 32 + mt * 16 + g;
            int row1 = row0 + 8;
            int col  = bn + wn * 32 + nt * 8 + t * 2;
            float bs0 = __ldg(bias + col), bs1 = __ldg(bias + col + 1);
            float v00 = fmaxf(acc[mt][nt][0] + bs0, 0.f);
            float v01 = fmaxf(acc[mt][nt][1] + bs1, 0.f);
            float v10 = fmaxf(acc[mt][nt][2] + bs0, 0.f);
            float v11 = fmaxf(acc[mt][nt][3] + bs1, 0.f);
            if (OUT_BF16) {
                __nv_bfloat16 h00 = __float2bfloat16(v00);
                __nv_bfloat16 h01 = __float2bfloat16(v01);
                __nv_bfloat16 h10 = __float2bfloat16(v10);
                __nv_bfloat16 h11 = __float2bfloat16(v11);
                __nv_bfloat162 H0 = {h00, h01}, H1 = {h10, h11};
                __nv_bfloat162 L0 = {
                    __float2bfloat16(v00 - __bfloat162float(h00)),
                    __float2bfloat16(v01 - __bfloat162float(h01))};
                __nv_bfloat162 L1 = {
                    __float2bfloat16(v10 - __bfloat162float(h10)),
                    __float2bfloat16(v11 - __bfloat162float(h11))};
                *(__nv_bfloat162*)(Chi + (size_t)row0 * N + col) = H0;
                *(__nv_bfloat162*)(Clo + (size_t)row0 * N + col) = L0;
                *(__nv_bfloat162*)(Chi + (size_t)row1 * N + col) = H1;
                *(__nv_bfloat162*)(Clo + (size_t)row1 * N + col) = L1;
            } else {
                *(float2*)(Cf + (size_t)row0 * N + col) = make_float2(v00, v01);
                *(float2*)(Cf + (size_t)row1 * N + col) = make_float2(v10, v11);
            }
        }
    }
}

// ---------------------------------------------------------------------------
// K7: per (b,n):  Tq = Tbar x_j q_,  Tqa = Tq x_k a_
// Writes TQA transposed as bf16 hi/lo: g_tqaT[b][c][n*16+ii], c=(q*10+a)*2+g
// smem: 8192 (Tbar, reused as sOut[16][284]) + 224 (q) + 160 (a) + 7168 (Tq)
// ---------------------------------------------------------------------------
__global__ __launch_bounds__(256)
void tq_tqa_kernel()
{
    extern __shared__ float sm[];
    float* sT  = sm;               // 8192 (reused as sOut after step A)
    float* sQ  = sm + 8192;        // 224
    float* sA  = sm + 8416;        // 160
    float* sTq = sm + 8576;        // 7168

    const int n   = blockIdx.x;
    const int b   = blockIdx.y;
    const int tid = threadIdx.x;

    const float4* Tp = (const float4*)g_Tbar;
    for (int i = tid; i < 2048; i += 256) ((float4*)sT)[i] = Tp[i];

    if (tid < 56) {
        int q  = tid >> 2;
        int j4 = (tid & 3) << 2;
        *(float4*)&sQ[q * 16 + j4] =
            *(const float4*)(g_q2 + (size_t)(b * NQ + q) * 512 + n * 16 + j4);
    }
    if (tid >= 64 && tid < 104) {
        int t  = tid - 64;
        int a  = t >> 2;
        int k4 = (t & 3) << 2;
        *(float4*)&sA[a * 16 + k4] =
            *(const float4*)(g_a2 + (size_t)(b * NA + a) * 512 + n * 16 + k4);
    }
    __syncthreads();

    // step A: Tq[q,i,k,g]
    {
        const int i_ = tid >> 4;
        const int k_ = tid & 15;
        float accx[14], accy[14];
        #pragma unroll
        for (int q = 0; q < 14; q++) { accx[q] = 0.f; accy[q] = 0.f; }
        #pragma unroll
        for (int j = 0; j < 16; j++) {
            float2 t2 = *(const float2*)&sT[(((i_ * 16 + j) * 16) + k_) * 2];
            #pragma unroll
            for (int q = 0; q < 14; q++) {
                float qv = sQ[q * 16 + j];
                accx[q] = fmaf(t2.x, qv, accx[q]);
                accy[q] = fmaf(t2.y, qv, accy[q]);
            }
        }
        #pragma unroll
        for (int q = 0; q < 14; q++)
            *(float2*)&sTq[((q * 16 + i_) * 16 + k_) * 2] =
                make_float2(accx[q], accy[q]);
    }
    __syncthreads();

    // step B: contract with a_, stash transposed in sOut[ii][c] (reuses sT)
    float* sOut = sT;   // [16][284]
    for (int t = tid; t < 2240; t += 256) {
        int ii  = t / 140;
        int rem = t - ii * 140;
        int q   = rem / 10;
        int a   = rem - q * 10;
        float sx = 0.f, sy = 0.f;
        #pragma unroll
        for (int k = 0; k < 16; k++) {
            float2 tq = *(const float2*)&sTq[((q * 16 + ii) * 16 + k) * 2];
            float  av = sA[a * 16 + k];
            sx = fmaf(tq.x, av, sx);
            sy = fmaf(tq.y, av, sy);
        }
        sOut[ii * 284 + rem * 2]     = sx;
        sOut[ii * 284 + rem * 2 + 1] = sy;
    }
    __syncthreads();

    // write bf16 hi/lo, coalesced 16B per (c, half)
    for (int idx = tid; idx < 560; idx += 256) {
        int c    = idx >> 1;
        int half = idx & 1;
        __nv_bfloat162 H[4], L[4];
        #pragma unroll
        for (int j = 0; j < 4; j++) {
            float v0 = sOut[(half * 8 + j * 2)     * 284 + c];
            float v1 = sOut[(half * 8 + j * 2 + 1) * 284 + c];
            __nv_bfloat16 h0 = __float2bfloat16(v0);
            __nv_bfloat16 h1 = __float2bfloat16(v1);
            H[j] = {h0, h1};
            L[j] = {__float2bfloat16(v0 - __bfloat162float(h0)),
                    __float2bfloat16(v1 - __bfloat162float(h1))};
        }
        size_t off = ((size_t)b * CPAD + c) * 512 + n * 16 + half * 8;
        *(uint4*)(g_tqaT_hi + off) = *(uint4*)H;
        *(uint4*)(g_tqaT_lo + off) = *(uint4*)L;
    }
}

// ---------------------------------------------------------------------------
// K8 (HMMA): out[b][v][c] = sum_k V2[b*100+v][k] * TQA_T[b][c][k]
// BM=128 (100 valid), BN=96, BK=32, 256 threads (8 warps 4x2, warp 32x48).
// grid (3, 128).
// ---------------------------------------------------------------------------
#define K8_STAGE 28672   // AH 8K, AL 8K, BH 6K, BL 6K
#define K8_SMEM  (2 * K8_STAGE)
#define K8_BH    16384
#define K8_BL    22528

__global__ __launch_bounds__(256, 1)
void k8_gemm(float* __restrict__ out)
{
    extern __shared__ char smem[];
    const uint32_t smb = smem_u32(smem);
    const int tid  = threadIdx.x;
    const int wid  = tid >> 5;
    const int lane = tid & 31;
    const int wm   = wid & 3;          // 4 warps along M (32 rows)
    const int wn   = wid >> 2;         // 2 warps along N (48 cols)
    const int bn   = blockIdx.x * 96;
    const int b    = blockIdx.y;

    const __nv_bfloat16* Ahi = g_v2_hi + (size_t)b * 100 * 512;
    const __nv_bfloat16* Alo = g_v2_lo + (size_t)b * 100 * 512;
    const __nv_bfloat16* Bhi = g_tqaT_hi + ((size_t)b * CPAD + bn) * 512;
    const __nv_bfloat16* Blo = g_tqaT_lo + ((size_t)b * CPAD + bn) * 512;

    auto load_stage = [&](int c) {
        const uint32_t sb = smb + (uint32_t)(c & 1) * K8_STAGE;
        const int k0 = c << 5;
        #pragma unroll
        for (int i = 0; i < 2; i++) {
            int idx = tid + i * 256;      // 0..511  (A: 128 rows x 4)
            int row = idx >> 2, cc = idx & 3;
            uint32_t so = swz_off(row, cc);
            size_t g = (size_t)row * 512 + k0 + cc * 8;
            cp16(sb + OFF_AH + so, Ahi + g);
            cp16(sb + OFF_AL + so, Alo + g);
        }
        {
            int idx = tid;                // B: 96 rows x 4 = 384 slots
            int row = idx >> 2, cc = idx & 3;
            uint32_t so = swz_off(row, cc);
            size_t g = (size_t)row * 512 + k0 + cc * 8;
            cp16(sb + K8_BH + so, Bhi + g);
            cp16(sb + K8_BL + so, Blo + g);
        }
        if (tid < 128) {
            int idx = tid + 256;
            int row = idx >> 2, cc = idx & 3;
            uint32_t so = swz_off(row, cc);
            size_t g = (size_t)row * 512 + k0 + cc * 8;
            cp16(sb + K8_BH + so, Bhi + g);
            cp16(sb + K8_BL + so, Blo + g);
        }
    };

    float acc[2][6][4];
    #pragma unroll
    for (int mt = 0; mt < 2; mt++)
        #pragma unroll
        for (int nt = 0; nt < 6; nt++)
            #pragma unroll
            for (int i = 0; i < 4; i++) acc[mt][nt][i] = 0.f;

    const int a_r = (lane & 7) | (((lane >> 3) & 1) << 3);
    const int a_c = lane >> 4;
    const int b_r = (lane & 7) | ((lane >> 4) << 3);
    const int b_c = (lane >> 3) & 1;

    load_stage(0);
    cp_commit();

    for (int c = 0; c < 16; c++) {
        if (c + 1 < 16) {
            load_stage(c + 1);
            cp_commit();
            cp_wait<1>();
        } else {
            cp_wait<0>();
        }
        __syncthreads();

        const uint32_t sb = smb + (uint32_t)(c & 1) * K8_STAGE;

        #pragma unroll
        for (int ks8 = 0; ks8 < 4; ks8 += 2) {
            uint32_t af_h[2][4], af_l[2][4];
            #pragma unroll
            for (int mt = 0; mt < 2; mt++) {
                int row = wm * 32 + mt * 16 + a_r;
                uint32_t so = swz_off(row, ks8 + a_c);
                ldsm4(af_h[mt], sb + OFF_AH + so);
                ldsm4(af_l[mt], sb + OFF_AL + so);
            }
            uint32_t bf_h[3][4], bf_l[3][4];
            #pragma unroll
            for (int nq = 0; nq < 3; nq++) {
                int row = wn * 48 + nq * 16 + b_r;
                uint32_t so = swz_off(row, ks8 + b_c);
                ldsm4(bf_h[nq], sb + K8_BH + so);
                ldsm4(bf_l[nq], sb + K8_BL + so);
            }
            #pragma unroll
            for (int mt = 0; mt < 2; mt++)
                #pragma unroll
                for (int nt = 0; nt < 6; nt++) {
                    const uint32_t* bh = &bf_h[nt >> 1][(nt & 1) * 2];
                    const uint32_t* bl = &bf_l[nt >> 1][(nt & 1) * 2];
                    mma_bf16(acc[mt][nt], af_h[mt], bh);
                    mma_bf16(acc[mt][nt], af_h[mt], bl);
                    mma_bf16(acc[mt][nt], af_l[mt], bh);
                }
        }
        __syncthreads();
    }

    // epilogue: predicated stores (v < 100, c < 280)
    const int g = lane >> 2;
    const int t = lane & 3;
    #pragma unroll
    for (int mt = 0; mt < 2; mt++) {
        #pragma unroll
        for (int nt = 0; nt < 6; nt++) {
            int v0 = wm * 32 + mt * 16 + g;
            int v1 = v0 + 8;
            int cg = bn + wn * 48 + nt * 8 + t * 2;
            if (cg < QAG) {
                if (v0 < NV)
                    *(float2*)(out + ((size_t)b * NV + v0) * QAG + cg) =
                        make_float2(acc[mt][nt][0], acc[mt][nt][1]);
                if (v1 < NV)
                    *(float2*)(out + ((size_t)b * NV + v1) * QAG + cg) =
                        make_float2(acc[mt][nt][2], acc[mt][nt][3]);
            }
        }
    }
}

// ---------------------------------------------------------------------------
extern "C" void kernel_launch(void* const* d_in, const int* in_sizes, int n_in,
                              void* d_out, int out_size)
{
    const float* v   = (const float*)d_in[0];
    const float* q   = (const float*)d_in[1];
    const float* a   = (const float*)d_in[2];
    const float* Wv  = (const float*)d_in[3];
    const float* bv  = (const float*)d_in[4];
    const float* Wq  = (const float*)d_in[5];
    const float* bq  = (const float*)d_in[6];
    const float* Wa  = (const float*)d_in[7];
    const float* ba  = (const float*)d_in[8];
    const float* Wvr = (const float*)d_in[9];
    const float* bvr = (const float*)d_in[10];
    const float* Wqr = (const float*)d_in[11];
    const float* bqr = (const float*)d_in[12];
    const float* War = (const float*)d_in[13];
    const float* bar = (const float*)d_in[14];
    const float* T   = (const float*)d_in[15];
    float* out       = (float*)d_out;

    __nv_bfloat16 *vhi,*vlo,*qhi,*qlo,*ahi,*alo;
    __nv_bfloat16 *Wvhi,*Wvlo,*Wqhi,*Wqlo,*Wahi,*Walo;
    __nv_bfloat16 *Wvrhi,*Wvrlo,*Wqrhi,*Wqrlo,*Warhi,*Warlo;
    __nv_bfloat16 *vthi,*vtlo,*qthi,*qtlo,*athi,*atlo,*v2hi,*v2lo;
    float *pq2,*pa2;
    cudaGetSymbolAddress((void**)&vhi, g_v_hi);   cudaGetSymbolAddress((void**)&vlo, g_v_lo);
    cudaGetSymbolAddress((void**)&qhi, g_q_hi);   cudaGetSymbolAddress((void**)&qlo, g_q_lo);
    cudaGetSymbolAddress((void**)&ahi, g_a_hi);   cudaGetSymbolAddress((void**)&alo, g_a_lo);
    cudaGetSymbolAddress((void**)&Wvhi, g_Wv_hi); cudaGetSymbolAddress((void**)&Wvlo, g_Wv_lo);
    cudaGetSymbolAddress((void**)&Wqhi, g_Wq_hi); cudaGetSymbolAddress((void**)&Wqlo, g_Wq_lo);
    cudaGetSymbolAddress((void**)&Wahi, g_Wa_hi); cudaGetSymbolAddress((void**)&Walo, g_Wa_lo);
    cudaGetSymbolAddress((void**)&Wvrhi, g_Wvr_hi); cudaGetSymbolAddress((void**)&Wvrlo, g_Wvr_lo);
    cudaGetSymbolAddress((void**)&Wqrhi, g_Wqr_hi); cudaGetSymbolAddress((void**)&Wqrlo, g_Wqr_lo);
    cudaGetSymbolAddress((void**)&Warhi, g_War_hi); cudaGetSymbolAddress((void**)&Warlo, g_War_lo);
    cudaGetSymbolAddress((void**)&vthi, g_vt_hi); cudaGetSymbolAddress((void**)&vtlo, g_vt_lo);
    cudaGetSymbolAddress((void**)&qthi, g_qt_hi); cudaGetSymbolAddress((void**)&qtlo, g_qt_lo);
    cudaGetSymbolAddress((void**)&athi, g_at_hi); cudaGetSymbolAddress((void**)&atlo, g_at_lo);
    cudaGetSymbolAddress((void**)&v2hi, g_v2_hi); cudaGetSymbolAddress((void**)&v2lo, g_v2_lo);
    cudaGetSymbolAddress((void**)&pq2, g_q2);
    cudaGetSymbolAddress((void**)&pa2, g_a2);

    cudaFuncSetAttribute(mma_gemm<0>, cudaFuncAttributeMaxDynamicSharedMemorySize, GEMM_SMEM);
    cudaFuncSetAttribute(mma_gemm<1>, cudaFuncAttributeMaxDynamicSharedMemorySize, GEMM_SMEM);
    cudaFuncSetAttribute(tq_tqa_kernel, cudaFuncAttributeMaxDynamicSharedMemorySize, 62976);
    cudaFuncSetAttribute(k8_gemm, cudaFuncAttributeMaxDynamicSharedMemorySize, K8_SMEM);

    auto split = [&](const float* x, __nv_bfloat16* h, __nv_bfloat16* l, int n) {
        int n4 = n / 4;
        split_bf16_kernel<<<(n4 + 255) / 256, 256>>>(x, h, l, n4);
    };

    // launches 1-3: inputs for the big GEMM
    split(v,   vhi,   vlo,   12800 * 2048);
    split(Wv,  Wvhi,  Wvlo,  512 * 2048);
    split(q,   qhi,   qlo,   1792  * 1024);

    // launch 4: stage-1 v projection (gets ncu-profiled)
    mma_gemm<1><<<dim3(4,100), 512, GEMM_SMEM>>>(vhi, vlo, Wvhi, Wvlo, bv,
                                                 nullptr, vthi, vtlo, 12800, 512, 2048);

    // remaining splits
    split(a,   ahi,   alo,   1280  * 1024);
    split(Wq,  Wqhi,  Wqlo,  512 * 1024);
    split(Wa,  Wahi,  Walo,  512 * 1024);
    split(Wvr, Wvrhi, Wvrlo, 512 * 512);
    split(Wqr, Wqrhi, Wqrlo, 512 * 512);
    split(War, Warhi, Warlo, 512 * 512);
    reduce_T_kernel<<<32, 256>>>(T);

    // stage 1 (q, a)
    mma_gemm<1><<<dim3(4,14), 512, GEMM_SMEM>>>(qhi, qlo, Wqhi, Wqlo, bq,
                                                nullptr, qthi, qtlo, 1792, 512, 1024);
    mma_gemm<1><<<dim3(4,10), 512, GEMM_SMEM>>>(ahi, alo, Wahi, Walo, ba,
                                                nullptr, athi, atlo, 1280, 512, 1024);

    // stage 2: v -> bf16 hi/lo (feeds K8); q,a -> fp32 (feed K7)
    mma_gemm<1><<<dim3(4,100), 512, GEMM_SMEM>>>(vthi, vtlo, Wvrhi, Wvrlo, bvr,
                                                 nullptr, v2hi, v2lo, 12800, 512, 512);
    mma_gemm<0><<<dim3(4,14),  512, GEMM_SMEM>>>(qthi, qtlo, Wqrhi, Wqrlo, bqr,
                                                 pq2, nullptr, nullptr, 1792, 512, 512);
    mma_gemm<0><<<dim3(4,10),  512, GEMM_SMEM>>>(athi, atlo, Warhi, Warlo, bar,
                                                 pa2, nullptr, nullptr, 1280, 512, 512);

    // stage 3: Tucker core contraction -> TQA_T (bf16 hi/lo)
    tq_tqa_kernel<<<dim3(RANK, Bb), 256, 62976>>>();

    // stage 4: batched HMMA GEMM -> output
    k8_gemm<<<dim3(3, Bb), 256, K8_SMEM>>>(out);
}

// round 6
// speedup vs baseline: 2.8215x; 1.0652x over previous
#include <cuda_runtime.h>
#include <cuda_bf16.h>
#include <cstdint>

// ---------------------------------------------------------------------------
// TCNet: B=128, NV=100, NQ=14, NA=10, V_DIM=2048, Q_DIM=1024, A_DIM=1024,
//        H_DIM=512, RANK=32, HD=16, G=2
//
// einsum 'rijkg,bnvi,bnqj,bnak->bvqag' : r and n are INDEPENDENT sums.
//   Tbar[i,j,k,g] = sum_r T[r,i,j,k,g]
//   out[b,v,q,a,g] = sum_{n,i,j,k} Tbar v_ q_ a_
//
// All big GEMMs run on mma.sync bf16 (HMMA) with bf16x3 fp32 emulation:
// hi*hi + hi*lo + lo*hi.
// GEMM config: 256 threads (8 warps 4x2, warp tile 32x64), 2 CTAs/SM.
// ---------------------------------------------------------------------------

#define Bb    128
#define NV    100
#define NQ    14
#define NA    10
#define RANK  32
#define G     2
#define QAG   (NQ*NA*G)   // 280
#define CPAD  288         // padded TQA_T row count

// ---------------- scratch (static device globals, zero-initialized) --------
__device__ __align__(256) __nv_bfloat16 g_v_hi [12800*2048], g_v_lo [12800*2048];
__device__ __align__(256) __nv_bfloat16 g_q_hi [1792*1024],  g_q_lo [1792*1024];
__device__ __align__(256) __nv_bfloat16 g_a_hi [1280*1024],  g_a_lo [1280*1024];
__device__ __align__(256) __nv_bfloat16 g_Wv_hi[512*2048],   g_Wv_lo[512*2048];
__device__ __align__(256) __nv_bfloat16 g_Wq_hi[512*1024],   g_Wq_lo[512*1024];
__device__ __align__(256) __nv_bfloat16 g_Wa_hi[512*1024],   g_Wa_lo[512*1024];
__device__ __align__(256) __nv_bfloat16 g_Wvr_hi[512*512],   g_Wvr_lo[512*512];
__device__ __align__(256) __nv_bfloat16 g_Wqr_hi[512*512],   g_Wqr_lo[512*512];
__device__ __align__(256) __nv_bfloat16 g_War_hi[512*512],   g_War_lo[512*512];
__device__ __align__(256) __nv_bfloat16 g_vt_hi[12800*512],  g_vt_lo[12800*512];
__device__ __align__(256) __nv_bfloat16 g_qt_hi[1792*512],   g_qt_lo[1792*512];
__device__ __align__(256) __nv_bfloat16 g_at_hi[1280*512],   g_at_lo[1280*512];
__device__ __align__(256) __nv_bfloat16 g_v2_hi[12832*512],  g_v2_lo[12832*512];
__device__ __align__(256) float g_q2[1792*512];
__device__ __align__(256) float g_a2[1280*512];
__device__ __align__(256) __nv_bfloat16 g_tqaT_hi[128*CPAD*512];
__device__ __align__(256) __nv_bfloat16 g_tqaT_lo[128*CPAD*512];
__device__ __align__(256) float g_Tbar[8192];

// ---------------- PTX helpers ----------------
__device__ __forceinline__ uint32_t smem_u32(const void* p) {
    uint32_t a;
    asm("{ .reg .u64 t; cvta.to.shared.u64 t, %1; cvt.u32.u64 %0, t; }"
        : "=r"(a) : "l"(p));
    return a;
}
__device__ __forceinline__ void mma_bf16(float* c, const uint32_t* a,
                                         const uint32_t* b) {
    asm volatile(
        "mma.sync.aligned.m16n8k16.row.col.f32.bf16.bf16.f32 "
        "{%0,%1,%2,%3}, {%4,%5,%6,%7}, {%8,%9}, {%0,%1,%2,%3};"
        : "+f"(c[0]), "+f"(c[1]), "+f"(c[2]), "+f"(c[3])
        : "r"(a[0]), "r"(a[1]), "r"(a[2]), "r"(a[3]), "r"(b[0]), "r"(b[1]));
}
__device__ __forceinline__ void ldsm4(uint32_t* r, uint32_t addr) {
    asm volatile("ldmatrix.sync.aligned.m8n8.x4.shared.b16 {%0,%1,%2,%3}, [%4];"
                 : "=r"(r[0]), "=r"(r[1]), "=r"(r[2]), "=r"(r[3]) : "r"(addr));
}
__device__ __forceinline__ void cp16(uint32_t dst, const void* src) {
    asm volatile("cp.async.cg.shared.global [%0], [%1], 16;"
                 :: "r"(dst), "l"(src));
}
__device__ __forceinline__ void cp_commit() {
    asm volatile("cp.async.commit_group;");
}
template<int N>
__device__ __forceinline__ void cp_wait() {
    asm volatile("cp.async.wait_group %0;" :: "n"(N));
}
__device__ __forceinline__ uint32_t swz_off(int row, int c) {
    return (uint32_t)(row * 64 + ((c ^ ((row >> 1) & 3)) << 4));
}

// ---------------------------------------------------------------------------
// split fp32 -> bf16 hi/lo (8 elements per thread)
// ---------------------------------------------------------------------------
__global__ void split_bf16_kernel(const float* __restrict__ x,
                                  __nv_bfloat16* __restrict__ hi,
                                  __nv_bfloat16* __restrict__ lo, int n8)
{
    int i = blockIdx.x * 256 + threadIdx.x;
    if (i >= n8) return;
    float4 v0 = ((const float4*)x)[i * 2];
    float4 v1 = ((const float4*)x)[i * 2 + 1];
    float f[8] = {v0.x, v0.y, v0.z, v0.w, v1.x, v1.y, v1.z, v1.w};
    __nv_bfloat162 H[4], L[4];
    #pragma unroll
    for (int j = 0; j < 4; j++) {
        __nv_bfloat16 h0 = __float2bfloat16(f[j*2]);
        __nv_bfloat16 h1 = __float2bfloat16(f[j*2+1]);
        H[j] = {h0, h1};
        L[j] = {__float2bfloat16(f[j*2]   - __bfloat162float(h0)),
                __float2bfloat16(f[j*2+1] - __bfloat162float(h1))};
    }
    ((uint4*)hi)[i] = *(uint4*)H;
    ((uint4*)lo)[i] = *(uint4*)L;
}

// ---------------------------------------------------------------------------
// Tbar[x] = sum_r T[r*8192 + x]
// ---------------------------------------------------------------------------
__global__ void reduce_T_kernel(const float* __restrict__ T)
{
    int x = blockIdx.x * 256 + threadIdx.x;
    float s = 0.f;
    #pragma unroll
    for (int r = 0; r < RANK; r++) s += T[(size_t)r * 8192 + x];
    g_Tbar[x] = s;
}

// ---------------------------------------------------------------------------
// HMMA bf16x3 GEMM: C[m,n] = relu( sum_k A[m,k]*W[n,k] + bias[n] )
// BM=128, BN=128, BK=32, 256 threads (8 warps 4x2, warp tile 32x64),
// cp.async double buffer, 2 CTAs/SM.
// ---------------------------------------------------------------------------
#define STAGE_SZ 32768
#define GEMM_SMEM (2 * STAGE_SZ)
#define OFF_AH 0
#define OFF_AL 8192
#define OFF_BH 16384
#define OFF_BL 24576

template<int OUT_BF16>
__global__ __launch_bounds__(256, 2)
void mma_gemm(const __nv_bfloat16* __restrict__ Ahi,
              const __nv_bfloat16* __restrict__ Alo,
              const __nv_bfloat16* __restrict__ Bhi,
              const __nv_bfloat16* __restrict__ Blo,
              const float* __restrict__ bias,
              float* __restrict__ Cf,
              __nv_bfloat16* __restrict__ Chi,
              __nv_bfloat16* __restrict__ Clo,
              int M, int N, int K)
{
    extern __shared__ char smem[];
    const uint32_t smb = smem_u32(smem);
    const int tid  = threadIdx.x;
    const int wid  = tid >> 5;
    const int lane = tid & 31;
    const int wm   = wid & 3;          // 4 warps along M (32 rows)
    const int wn   = wid >> 2;         // 2 warps along N (64 cols)
    const int bm   = blockIdx.y * 128;
    const int bn   = blockIdx.x * 128;

    const int nchunks = K >> 5;

    auto load_stage = [&](int c) {
        const uint32_t sb = smb + (uint32_t)(c & 1) * STAGE_SZ;
        const int k0 = c << 5;
        #pragma unroll
        for (int i = 0; i < 2; i++) {
            int idx = tid + i * 256;         // 0..511
            int row = idx >> 2;
            int cc  = idx & 3;
            uint32_t so = swz_off(row, cc);
            size_t gA = (size_t)(bm + row) * K + k0 + cc * 8;
            size_t gB = (size_t)(bn + row) * K + k0 + cc * 8;
            cp16(sb + OFF_AH + so, Ahi + gA);
            cp16(sb + OFF_AL + so, Alo + gA);
            cp16(sb + OFF_BH + so, Bhi + gB);
            cp16(sb + OFF_BL + so, Blo + gB);
        }
    };

    float acc[2][8][4];
    #pragma unroll
    for (int mt = 0; mt < 2; mt++)
        #pragma unroll
        for (int nt = 0; nt < 8; nt++)
            #pragma unroll
            for (int i = 0; i < 4; i++) acc[mt][nt][i] = 0.f;

    const int a_r = (lane & 7) | (((lane >> 3) & 1) << 3);
    const int a_c = lane >> 4;
    const int b_r = (lane & 7) | ((lane >> 4) << 3);
    const int b_c = (lane >> 3) & 1;

    load_stage(0);
    cp_commit();

    for (int c = 0; c < nchunks; c++) {
        if (c + 1 < nchunks) {
            load_stage(c + 1);
            cp_commit();
            cp_wait<1>();
        } else {
            cp_wait<0>();
        }
        __syncthreads();

        const uint32_t sb = smb + (uint32_t)(c & 1) * STAGE_SZ;

        #pragma unroll
        for (int ks8 = 0; ks8 < 4; ks8 += 2) {
            uint32_t af_h[2][4], af_l[2][4];
            #pragma unroll
            for (int mt = 0; mt < 2; mt++) {
                int row = wm * 32 + mt * 16 + a_r;
                uint32_t so = swz_off(row, ks8 + a_c);
                ldsm4(af_h[mt], sb + OFF_AH + so);
                ldsm4(af_l[mt], sb + OFF_AL + so);
            }
            // per-nq B fragments (keeps register pressure low)
            #pragma unroll
            for (int nq = 0; nq < 4; nq++) {
                uint32_t bf_h[4], bf_l[4];
                int row = wn * 64 + nq * 16 + b_r;
                uint32_t so = swz_off(row, ks8 + b_c);
                ldsm4(bf_h, sb + OFF_BH + so);
                ldsm4(bf_l, sb + OFF_BL + so);
                #pragma unroll
                for (int mt = 0; mt < 2; mt++)
                    #pragma unroll
                    for (int h = 0; h < 2; h++) {
                        float* ac = acc[mt][nq * 2 + h];
                        mma_bf16(ac, af_h[mt], &bf_h[h * 2]);
                        mma_bf16(ac, af_h[mt], &bf_l[h * 2]);
                        mma_bf16(ac, af_l[mt], &bf_h[h * 2]);
                    }
            }
        }
        __syncthreads();
    }

    // epilogue: bias + relu
    const int g = lane >> 2;
    const int t = lane & 3;
    #pragma unroll
    for (int mt = 0; mt < 2; mt++) {
        #pragma unroll
        for (int nt = 0; nt < 8; nt++) {
            int row0 = bm + wm * 32 + mt * 16 + g;
            int row1 = row0 + 8;
            int col  = bn + wn * 64 + nt * 8 + t * 2;
            float bs0 = __ldg(bias + col), bs1 = __ldg(bias + col + 1);
            float v00 = fmaxf(acc[mt][nt][0] + bs0, 0.f);
            float v01 = fmaxf(acc[mt][nt][1] + bs1, 0.f);
            float v10 = fmaxf(acc[mt][nt][2] + bs0, 0.f);
            float v11 = fmaxf(acc[mt][nt][3] + bs1, 0.f);
            if (OUT_BF16) {
                __nv_bfloat16 h00 = __float2bfloat16(v00);
                __nv_bfloat16 h01 = __float2bfloat16(v01);
                __nv_bfloat16 h10 = __float2bfloat16(v10);
                __nv_bfloat16 h11 = __float2bfloat16(v11);
                __nv_bfloat162 H0 = {h00, h01}, H1 = {h10, h11};
                __nv_bfloat162 L0 = {
                    __float2bfloat16(v00 - __bfloat162float(h00)),
                    __float2bfloat16(v01 - __bfloat162float(h01))};
                __nv_bfloat162 L1 = {
                    __float2bfloat16(v10 - __bfloat162float(h10)),
                    __float2bfloat16(v11 - __bfloat162float(h11))};
                *(__nv_bfloat162*)(Chi + (size_t)row0 * N + col) = H0;
                *(__nv_bfloat162*)(Clo + (size_t)row0 * N + col) = L0;
                *(__nv_bfloat162*)(Chi + (size_t)row1 * N + col) = H1;
                *(__nv_bfloat162*)(Clo + (size_t)row1 * N + col) = L1;
            } else {
                *(float2*)(Cf + (size_t)row0 * N + col) = make_float2(v00, v01);
                *(float2*)(Cf + (size_t)row1 * N + col) = make_float2(v10, v11);
            }
        }
    }
}

// ---------------------------------------------------------------------------
// K7: per (b,n):  Tq = Tbar x_j q_,  Tqa = Tq x_k a_
// Writes TQA transposed as bf16 hi/lo: g_tqaT[b][c][n*16+ii], c=(q*10+a)*2+g
// ---------------------------------------------------------------------------
__global__ __launch_bounds__(256)
void tq_tqa_kernel()
{
    extern __shared__ float sm[];
    float* sT  = sm;               // 8192 (reused as sOut after step A)
    float* sQ  = sm + 8192;        // 224
    float* sA  = sm + 8416;        // 160
    float* sTq = sm + 8576;        // 7168

    const int n   = blockIdx.x;
    const int b   = blockIdx.y;
    const int tid = threadIdx.x;

    const float4* Tp = (const float4*)g_Tbar;
    for (int i = tid; i < 2048; i += 256) ((float4*)sT)[i] = Tp[i];

    if (tid < 56) {
        int q  = tid >> 2;
        int j4 = (tid & 3) << 2;
        *(float4*)&sQ[q * 16 + j4] =
            *(const float4*)(g_q2 + (size_t)(b * NQ + q) * 512 + n * 16 + j4);
    }
    if (tid >= 64 && tid < 104) {
        int t  = tid - 64;
        int a  = t >> 2;
        int k4 = (t & 3) << 2;
        *(float4*)&sA[a * 16 + k4] =
            *(const float4*)(g_a2 + (size_t)(b * NA + a) * 512 + n * 16 + k4);
    }
    __syncthreads();

    // step A: Tq[q,i,k,g]
    {
        const int i_ = tid >> 4;
        const int k_ = tid & 15;
        float accx[14], accy[14];
        #pragma unroll
        for (int q = 0; q < 14; q++) { accx[q] = 0.f; accy[q] = 0.f; }
        #pragma unroll
        for (int j = 0; j < 16; j++) {
            float2 t2 = *(const float2*)&sT[(((i_ * 16 + j) * 16) + k_) * 2];
            #pragma unroll
            for (int q = 0; q < 14; q++) {
                float qv = sQ[q * 16 + j];
                accx[q] = fmaf(t2.x, qv, accx[q]);
                accy[q] = fmaf(t2.y, qv, accy[q]);
            }
        }
        #pragma unroll
        for (int q = 0; q < 14; q++)
            *(float2*)&sTq[((q * 16 + i_) * 16 + k_) * 2] =
                make_float2(accx[q], accy[q]);
    }
    __syncthreads();

    // step B: contract with a_, stash transposed in sOut[ii][c]
    float* sOut = sT;   // [16][284]
    for (int t = tid; t < 2240; t += 256) {
        int ii  = t / 140;
        int rem = t - ii * 140;
        int q   = rem / 10;
        int a   = rem - q * 10;
        float sx = 0.f, sy = 0.f;
        #pragma unroll
        for (int k = 0; k < 16; k++) {
            float2 tq = *(const float2*)&sTq[((q * 16 + ii) * 16 + k) * 2];
            float  av = sA[a * 16 + k];
            sx = fmaf(tq.x, av, sx);
            sy = fmaf(tq.y, av, sy);
        }
        sOut[ii * 284 + rem * 2]     = sx;
        sOut[ii * 284 + rem * 2 + 1] = sy;
    }
    __syncthreads();

    for (int idx = tid; idx < 560; idx += 256) {
        int c    = idx >> 1;
        int half = idx & 1;
        __nv_bfloat162 H[4], L[4];
        #pragma unroll
        for (int j = 0; j < 4; j++) {
            float v0 = sOut[(half * 8 + j * 2)     * 284 + c];
            float v1 = sOut[(half * 8 + j * 2 + 1) * 284 + c];
            __nv_bfloat16 h0 = __float2bfloat16(v0);
            __nv_bfloat16 h1 = __float2bfloat16(v1);
            H[j] = {h0, h1};
            L[j] = {__float2bfloat16(v0 - __bfloat162float(h0)),
                    __float2bfloat16(v1 - __bfloat162float(h1))};
        }
        size_t off = ((size_t)b * CPAD + c) * 512 + n * 16 + half * 8;
        *(uint4*)(g_tqaT_hi + off) = *(uint4*)H;
        *(uint4*)(g_tqaT_lo + off) = *(uint4*)L;
    }
}

// ---------------------------------------------------------------------------
// K8 (HMMA): out[b][v][c] = sum_k V2[b*100+v][k] * TQA_T[b][c][k]
// BM=128 (100 valid), BN=96, BK=32, 256 threads (8 warps 4x2, warp 32x48).
// ---------------------------------------------------------------------------
#define K8_STAGE 28672
#define K8_SMEM  (2 * K8_STAGE)
#define K8_BH    16384
#define K8_BL    22528

__global__ __launch_bounds__(256, 2)
void k8_gemm(float* __restrict__ out)
{
    extern __shared__ char smem[];
    const uint32_t smb = smem_u32(smem);
    const int tid  = threadIdx.x;
    const int wid  = tid >> 5;
    const int lane = tid & 31;
    const int wm   = wid & 3;
    const int wn   = wid >> 2;
    const int bn   = blockIdx.x * 96;
    const int b    = blockIdx.y;

    const __nv_bfloat16* Ahi = g_v2_hi + (size_t)b * 100 * 512;
    const __nv_bfloat16* Alo = g_v2_lo + (size_t)b * 100 * 512;
    const __nv_bfloat16* Bhi = g_tqaT_hi + ((size_t)b * CPAD + bn) * 512;
    const __nv_bfloat16* Blo = g_tqaT_lo + ((size_t)b * CPAD + bn) * 512;

    auto load_stage = [&](int c) {
        const uint32_t sb = smb + (uint32_t)(c & 1) * K8_STAGE;
        const int k0 = c << 5;
        #pragma unroll
        for (int i = 0; i < 2; i++) {
            int idx = tid + i * 256;
            int row = idx >> 2, cc = idx & 3;
            uint32_t so = swz_off(row, cc);
            size_t g = (size_t)row * 512 + k0 + cc * 8;
            cp16(sb + OFF_AH + so, Ahi + g);
            cp16(sb + OFF_AL + so, Alo + g);
        }
        {
            int idx = tid;
            int row = idx >> 2, cc = idx & 3;
            uint32_t so = swz_off(row, cc);
            size_t g = (size_t)row * 512 + k0 + cc * 8;
            cp16(sb + K8_BH + so, Bhi + g);
            cp16(sb + K8_BL + so, Blo + g);
        }
        if (tid < 128) {
            int idx = tid + 256;
            int row = idx >> 2, cc = idx & 3;
            uint32_t so = swz_off(row, cc);
            size_t g = (size_t)row * 512 + k0 + cc * 8;
            cp16(sb + K8_BH + so, Bhi + g);
            cp16(sb + K8_BL + so, Blo + g);
        }
    };

    float acc[2][6][4];
    #pragma unroll
    for (int mt = 0; mt < 2; mt++)
        #pragma unroll
        for (int nt = 0; nt < 6; nt++)
            #pragma unroll
            for (int i = 0; i < 4; i++) acc[mt][nt][i] = 0.f;

    const int a_r = (lane & 7) | (((lane >> 3) & 1) << 3);
    const int a_c = lane >> 4;
    const int b_r = (lane & 7) | ((lane >> 4) << 3);
    const int b_c = (lane >> 3) & 1;

    load_stage(0);
    cp_commit();

    for (int c = 0; c < 16; c++) {
        if (c + 1 < 16) {
            load_stage(c + 1);
            cp_commit();
            cp_wait<1>();
        } else {
            cp_wait<0>();
        }
        __syncthreads();

        const uint32_t sb = smb + (uint32_t)(c & 1) * K8_STAGE;

        #pragma unroll
        for (int ks8 = 0; ks8 < 4; ks8 += 2) {
            uint32_t af_h[2][4], af_l[2][4];
            #pragma unroll
            for (int mt = 0; mt < 2; mt++) {
                int row = wm * 32 + mt * 16 + a_r;
                uint32_t so = swz_off(row, ks8 + a_c);
                ldsm4(af_h[mt], sb + OFF_AH + so);
                ldsm4(af_l[mt], sb + OFF_AL + so);
            }
            #pragma unroll
            for (int nq = 0; nq < 3; nq++) {
                uint32_t bf_h[4], bf_l[4];
                int row = wn * 48 + nq * 16 + b_r;
                uint32_t so = swz_off(row, ks8 + b_c);
                ldsm4(bf_h, sb + K8_BH + so);
                ldsm4(bf_l, sb + K8_BL + so);
                #pragma unroll
                for (int mt = 0; mt < 2; mt++)
                    #pragma unroll
                    for (int h = 0; h < 2; h++) {
                        float* ac = acc[mt][nq * 2 + h];
                        mma_bf16(ac, af_h[mt], &bf_h[h * 2]);
                        mma_bf16(ac, af_h[mt], &bf_l[h * 2]);
                        mma_bf16(ac, af_l[mt], &bf_h[h * 2]);
                    }
            }
        }
        __syncthreads();
    }

    const int g = lane >> 2;
    const int t = lane & 3;
    #pragma unroll
    for (int mt = 0; mt < 2; mt++) {
        #pragma unroll
        for (int nt = 0; nt < 6; nt++) {
            int v0 = wm * 32 + mt * 16 + g;
            int v1 = v0 + 8;
            int cg = bn + wn * 48 + nt * 8 + t * 2;
            if (cg < QAG) {
                if (v0 < NV)
                    *(float2*)(out + ((size_t)b * NV + v0) * QAG + cg) =
                        make_float2(acc[mt][nt][0], acc[mt][nt][1]);
                if (v1 < NV)
                    *(float2*)(out + ((size_t)b * NV + v1) * QAG + cg) =
                        make_float2(acc[mt][nt][2], acc[mt][nt][3]);
            }
        }
    }
}

// ---------------------------------------------------------------------------
extern "C" void kernel_launch(void* const* d_in, const int* in_sizes, int n_in,
                              void* d_out, int out_size)
{
    const float* v   = (const float*)d_in[0];
    const float* q   = (const float*)d_in[1];
    const float* a   = (const float*)d_in[2];
    const float* Wv  = (const float*)d_in[3];
    const float* bv  = (const float*)d_in[4];
    const float* Wq  = (const float*)d_in[5];
    const float* bq  = (const float*)d_in[6];
    const float* Wa  = (const float*)d_in[7];
    const float* ba  = (const float*)d_in[8];
    const float* Wvr = (const float*)d_in[9];
    const float* bvr = (const float*)d_in[10];
    const float* Wqr = (const float*)d_in[11];
    const float* bqr = (const float*)d_in[12];
    const float* War = (const float*)d_in[13];
    const float* bar = (const float*)d_in[14];
    const float* T   = (const float*)d_in[15];
    float* out       = (float*)d_out;

    __nv_bfloat16 *vhi,*vlo,*qhi,*qlo,*ahi,*alo;
    __nv_bfloat16 *Wvhi,*Wvlo,*Wqhi,*Wqlo,*Wahi,*Walo;
    __nv_bfloat16 *Wvrhi,*Wvrlo,*Wqrhi,*Wqrlo,*Warhi,*Warlo;
    __nv_bfloat16 *vthi,*vtlo,*qthi,*qtlo,*athi,*atlo,*v2hi,*v2lo;
    float *pq2,*pa2;
    cudaGetSymbolAddress((void**)&vhi, g_v_hi);   cudaGetSymbolAddress((void**)&vlo, g_v_lo);
    cudaGetSymbolAddress((void**)&qhi, g_q_hi);   cudaGetSymbolAddress((void**)&qlo, g_q_lo);
    cudaGetSymbolAddress((void**)&ahi, g_a_hi);   cudaGetSymbolAddress((void**)&alo, g_a_lo);
    cudaGetSymbolAddress((void**)&Wvhi, g_Wv_hi); cudaGetSymbolAddress((void**)&Wvlo, g_Wv_lo);
    cudaGetSymbolAddress((void**)&Wqhi, g_Wq_hi); cudaGetSymbolAddress((void**)&Wqlo, g_Wq_lo);
    cudaGetSymbolAddress((void**)&Wahi, g_Wa_hi); cudaGetSymbolAddress((void**)&Walo, g_Wa_lo);
    cudaGetSymbolAddress((void**)&Wvrhi, g_Wvr_hi); cudaGetSymbolAddress((void**)&Wvrlo, g_Wvr_lo);
    cudaGetSymbolAddress((void**)&Wqrhi, g_Wqr_hi); cudaGetSymbolAddress((void**)&Wqrlo, g_Wqr_lo);
    cudaGetSymbolAddress((void**)&Warhi, g_War_hi); cudaGetSymbolAddress((void**)&Warlo, g_War_lo);
    cudaGetSymbolAddress((void**)&vthi, g_vt_hi); cudaGetSymbolAddress((void**)&vtlo, g_vt_lo);
    cudaGetSymbolAddress((void**)&qthi, g_qt_hi); cudaGetSymbolAddress((void**)&qtlo, g_qt_lo);
    cudaGetSymbolAddress((void**)&athi, g_at_hi); cudaGetSymbolAddress((void**)&atlo, g_at_lo);
    cudaGetSymbolAddress((void**)&v2hi, g_v2_hi); cudaGetSymbolAddress((void**)&v2lo, g_v2_lo);
    cudaGetSymbolAddress((void**)&pq2, g_q2);
    cudaGetSymbolAddress((void**)&pa2, g_a2);

    cudaFuncSetAttribute(mma_gemm<0>, cudaFuncAttributeMaxDynamicSharedMemorySize, GEMM_SMEM);
    cudaFuncSetAttribute(mma_gemm<1>, cudaFuncAttributeMaxDynamicSharedMemorySize, GEMM_SMEM);
    cudaFuncSetAttribute(tq_tqa_kernel, cudaFuncAttributeMaxDynamicSharedMemorySize, 62976);
    cudaFuncSetAttribute(k8_gemm, cudaFuncAttributeMaxDynamicSharedMemorySize, K8_SMEM);

    auto split = [&](const float* x, __nv_bfloat16* h, __nv_bfloat16* l, int n) {
        int n8 = n / 8;
        split_bf16_kernel<<<(n8 + 255) / 256, 256>>>(x, h, l, n8);
    };

    // launches 1-3: inputs for the big GEMM
    split(v,   vhi,   vlo,   12800 * 2048);
    split(Wv,  Wvhi,  Wvlo,  512 * 2048);
    split(q,   qhi,   qlo,   1792  * 1024);

    // launch 4: stage-1 v projection (gets ncu-profiled)
    mma_gemm<1><<<dim3(4,100), 256, GEMM_SMEM>>>(vhi, vlo, Wvhi, Wvlo, bv,
                                                 nullptr, vthi, vtlo, 12800, 512, 2048);

    split(a,   ahi,   alo,   1280  * 1024);
    split(Wq,  Wqhi,  Wqlo,  512 * 1024);
    split(Wa,  Wahi,  Walo,  512 * 1024);
    split(Wvr, Wvrhi, Wvrlo, 512 * 512);
    split(Wqr, Wqrhi, Wqrlo, 512 * 512);
    split(War, Warhi, Warlo, 512 * 512);
    reduce_T_kernel<<<32, 256>>>(T);

    // stage 1 (q, a)
    mma_gemm<1><<<dim3(4,14), 256, GEMM_SMEM>>>(qhi, qlo, Wqhi, Wqlo, bq,
                                                nullptr, qthi, qtlo, 1792, 512, 1024);
    mma_gemm<1><<<dim3(4,10), 256, GEMM_SMEM>>>(ahi, alo, Wahi, Walo, ba,
                                                nullptr, athi, atlo, 1280, 512, 1024);

    // stage 2
    mma_gemm<1><<<dim3(4,100), 256, GEMM_SMEM>>>(vthi, vtlo, Wvrhi, Wvrlo, bvr,
                                                 nullptr, v2hi, v2lo, 12800, 512, 512);
    mma_gemm<0><<<dim3(4,14),  256, GEMM_SMEM>>>(qthi, qtlo, Wqrhi, Wqrlo, bqr,
                                                 pq2, nullptr, nullptr, 1792, 512, 512);
    mma_gemm<0><<<dim3(4,10),  256, GEMM_SMEM>>>(athi, atlo, Warhi, Warlo, bar,
                                                 pa2, nullptr, nullptr, 1280, 512, 512);

    // stage 3: Tucker core contraction -> TQA_T (bf16 hi/lo)
    tq_tqa_kernel<<<dim3(RANK, Bb), 256, 62976>>>();

    // stage 4: batched HMMA GEMM -> output
    k8_gemm<<<dim3(3, Bb), 256, K8_SMEM>>>(out);
}